// round 2
// baseline (speedup 1.0000x reference)
#include <cuda_runtime.h>
#include <math.h>

#define NN   50000
#define FH   128
#define ESMAX 400000

// ---------------- scratch (static device globals; no allocation) ----------------
__device__ float g_agg[(size_t)NN * FH];          // 25.6 MB  neighbor-sum buffer
__device__ float g_h1[(size_t)NN * FH];           // 25.6 MB  layer-1 output
__device__ float g_hstack[(size_t)4 * NN * FH];   // 102.4 MB per-metapath layer-2 outputs
__device__ float g_emb[(size_t)NN * FH];          // 25.6 MB  attention-weighted node emb
__device__ float g_deg[NN];
__device__ float g_invdeg[NN];
__device__ float g_he[(size_t)ESMAX * FH];        // 204.8 MB edge MLP hidden

// ---------------- degree ----------------
__global__ void deg_kernel(const int* __restrict__ dst, int ne) {
    int i = blockIdx.x * blockDim.x + threadIdx.x;
    if (i < ne) atomicAdd(&g_deg[dst[i]], 1.0f);
}

__global__ void invdeg_kernel() {
    int i = blockIdx.x * blockDim.x + threadIdx.x;
    if (i < NN) g_invdeg[i] = 1.0f / fmaxf(g_deg[i], 1.0f);
}

// ---------------- scatter-add: agg[dst] += h[src], one warp per edge ----------------
__global__ void scatter_kernel(const float* __restrict__ h, const int* __restrict__ src,
                               const int* __restrict__ dst, int ne) {
    int w = (blockIdx.x * blockDim.x + threadIdx.x) >> 5;
    if (w >= ne) return;
    int lane = threadIdx.x & 31;
    int s = src[w], d = dst[w];
    float4 v = *(const float4*)(h + (size_t)s * FH + lane * 4);
    float* p = g_agg + (size_t)d * FH + lane * 4;
    atomicAdd(p + 0, v.x);
    atomicAdd(p + 1, v.y);
    atomicAdd(p + 2, v.z);
    atomicAdd(p + 3, v.w);
}

// ---------------- fused SAGE layer GEMM ----------------
// Out[n,:] = act( Xs[n,:]@Wself + (g_agg[n,:]*g_invdeg[n])@Wneigh + bias )
// Tiled 128x128, K=256 virtual (two 128-halves), 256 threads, 8x8 micro-tile.
template <bool RELU>
__global__ void __launch_bounds__(256, 2) sage_gemm_kernel(
    const float* __restrict__ Xs,
    const float* __restrict__ Wself, const float* __restrict__ Wneigh,
    const float* __restrict__ bias,
    float* __restrict__ Out, int nrows)
{
    __shared__ float As[16][128];   // [kk][row]
    __shared__ float Bs[16][128];   // [kk][col]
    const int tid  = threadIdx.x;
    const int row0 = blockIdx.x * 128;
    const int ty = tid >> 4, tx = tid & 15;

    // A-load mapping: thread loads 8 contiguous k for one row
    const int ar  = tid >> 1;            // 0..127
    const int akk = (tid & 1) * 8;       // 0 or 8
    const int grow = row0 + ar;
    const bool avalid = grow < nrows;
    const float* xrow = Xs   + (size_t)(avalid ? grow : 0) * FH;
    const float* nrow = g_agg + (size_t)(avalid ? grow : 0) * FH;
    const float inv   = avalid ? g_invdeg[grow] : 0.0f;

    // B-load mapping
    const int bkk  = tid >> 4;           // 0..15
    const int bcol = (tid & 15) * 8;

    float acc[8][8];
#pragma unroll
    for (int i = 0; i < 8; ++i)
#pragma unroll
        for (int j = 0; j < 8; ++j) acc[i][j] = 0.0f;

#pragma unroll 1
    for (int half = 0; half < 2; ++half) {
        const float* Arow = half ? nrow : xrow;
        const float* Wmat = half ? Wneigh : Wself;
        const float  sc   = half ? inv : 1.0f;
#pragma unroll 1
        for (int kt = 0; kt < 8; ++kt) {
            const int k0 = kt * 16;
            // stage A
            float va[8];
            if (avalid) {
                float4 a = *(const float4*)(Arow + k0 + akk);
                float4 b = *(const float4*)(Arow + k0 + akk + 4);
                va[0] = a.x * sc; va[1] = a.y * sc; va[2] = a.z * sc; va[3] = a.w * sc;
                va[4] = b.x * sc; va[5] = b.y * sc; va[6] = b.z * sc; va[7] = b.w * sc;
            } else {
#pragma unroll
                for (int i = 0; i < 8; ++i) va[i] = 0.0f;
            }
            // stage B
            const float* W = Wmat + (size_t)(k0 + bkk) * FH + bcol;
            float4 wa = *(const float4*)W;
            float4 wb = *(const float4*)(W + 4);

            __syncthreads();
#pragma unroll
            for (int i = 0; i < 8; ++i) As[akk + i][ar] = va[i];
            Bs[bkk][bcol + 0] = wa.x; Bs[bkk][bcol + 1] = wa.y;
            Bs[bkk][bcol + 2] = wa.z; Bs[bkk][bcol + 3] = wa.w;
            Bs[bkk][bcol + 4] = wb.x; Bs[bkk][bcol + 5] = wb.y;
            Bs[bkk][bcol + 6] = wb.z; Bs[bkk][bcol + 7] = wb.w;
            __syncthreads();

#pragma unroll
            for (int kk = 0; kk < 16; ++kk) {
                float af[8], bf[8];
                *(float4*)(af)     = *(const float4*)&As[kk][ty * 8];
                *(float4*)(af + 4) = *(const float4*)&As[kk][ty * 8 + 4];
                *(float4*)(bf)     = *(const float4*)&Bs[kk][tx * 8];
                *(float4*)(bf + 4) = *(const float4*)&Bs[kk][tx * 8 + 4];
#pragma unroll
                for (int i = 0; i < 8; ++i)
#pragma unroll
                    for (int j = 0; j < 8; ++j) acc[i][j] += af[i] * bf[j];
            }
        }
    }

    float bv[8];
    *(float4*)(bv)     = *(const float4*)(bias + tx * 8);
    *(float4*)(bv + 4) = *(const float4*)(bias + tx * 8 + 4);
#pragma unroll
    for (int i = 0; i < 8; ++i) {
        int r = row0 + ty * 8 + i;
        if (r < nrows) {
            float o[8];
#pragma unroll
            for (int j = 0; j < 8; ++j) {
                float v = acc[i][j] + bv[j];
                if (RELU) v = fmaxf(v, 0.0f);
                o[j] = v;
            }
            *(float4*)(Out + (size_t)r * FH + tx * 8)     = *(float4*)(o);
            *(float4*)(Out + (size_t)r * FH + tx * 8 + 4) = *(float4*)(o + 4);
        }
    }
}

// ---------------- metapath attention + weighted sum ----------------
// one warp per node
__global__ void attention_kernel(const float* __restrict__ attW, const float* __restrict__ attB) {
    int n = (blockIdx.x * blockDim.x + threadIdx.x) >> 5;
    if (n >= NN) return;
    int lane = threadIdx.x & 31;

    float4 hv[4];
    float logit[4];
#pragma unroll
    for (int k = 0; k < 4; ++k) {
        float4 h4 = *(const float4*)(g_hstack + ((size_t)k * NN + n) * FH + lane * 4);
        float4 w4 = *(const float4*)(attW + k * FH + lane * 4);
        hv[k] = h4;
        float p = h4.x * w4.x + h4.y * w4.y + h4.z * w4.z + h4.w * w4.w;
#pragma unroll
        for (int o = 16; o; o >>= 1) p += __shfl_xor_sync(0xffffffffu, p, o);
        logit[k] = p + attB[k];
    }
    float m = fmaxf(fmaxf(logit[0], logit[1]), fmaxf(logit[2], logit[3]));
    float e[4], s = 0.0f;
#pragma unroll
    for (int k = 0; k < 4; ++k) { e[k] = expf(logit[k] - m); s += e[k]; }
    float is = 1.0f / s;
    float4 o = make_float4(0.f, 0.f, 0.f, 0.f);
#pragma unroll
    for (int k = 0; k < 4; ++k) {
        float w = e[k] * is;
        o.x += w * hv[k].x; o.y += w * hv[k].y; o.z += w * hv[k].z; o.w += w * hv[k].w;
    }
    *(float4*)(g_emb + (size_t)n * FH + lane * 4) = o;
}

// ---------------- edge-scorer GEMM: he = relu([emb[src]|emb[dst]] @ W + b) ----------------
__global__ void __launch_bounds__(256, 2) edge_gemm_kernel(
    const int* __restrict__ src, const int* __restrict__ dst,
    const float* __restrict__ W /*[256,128]*/, const float* __restrict__ bias, int ne)
{
    __shared__ float As[16][128];
    __shared__ float Bs[16][128];
    __shared__ int   sIdx[2][128];
    const int tid  = threadIdx.x;
    const int row0 = blockIdx.x * 128;
    const int ty = tid >> 4, tx = tid & 15;

    if (tid < 128) {
        int e = row0 + tid;
        sIdx[0][tid] = (e < ne) ? src[e] : 0;
        sIdx[1][tid] = (e < ne) ? dst[e] : 0;
    }
    __syncthreads();

    const int ar  = tid >> 1;
    const int akk = (tid & 1) * 8;
    const bool avalid = (row0 + ar) < ne;
    const float* rowbase[2];
    rowbase[0] = g_emb + (size_t)sIdx[0][ar] * FH;
    rowbase[1] = g_emb + (size_t)sIdx[1][ar] * FH;

    const int bkk  = tid >> 4;
    const int bcol = (tid & 15) * 8;

    float acc[8][8];
#pragma unroll
    for (int i = 0; i < 8; ++i)
#pragma unroll
        for (int j = 0; j < 8; ++j) acc[i][j] = 0.0f;

#pragma unroll 1
    for (int half = 0; half < 2; ++half) {
        const float* Arow = rowbase[half];
        const float* Wh   = W + (size_t)half * FH * FH;
#pragma unroll 1
        for (int kt = 0; kt < 8; ++kt) {
            const int k0 = kt * 16;
            float va[8];
            if (avalid) {
                float4 a = *(const float4*)(Arow + k0 + akk);
                float4 b = *(const float4*)(Arow + k0 + akk + 4);
                va[0] = a.x; va[1] = a.y; va[2] = a.z; va[3] = a.w;
                va[4] = b.x; va[5] = b.y; va[6] = b.z; va[7] = b.w;
            } else {
#pragma unroll
                for (int i = 0; i < 8; ++i) va[i] = 0.0f;
            }
            const float* Wp = Wh + (size_t)(k0 + bkk) * FH + bcol;
            float4 wa = *(const float4*)Wp;
            float4 wb = *(const float4*)(Wp + 4);

            __syncthreads();
#pragma unroll
            for (int i = 0; i < 8; ++i) As[akk + i][ar] = va[i];
            Bs[bkk][bcol + 0] = wa.x; Bs[bkk][bcol + 1] = wa.y;
            Bs[bkk][bcol + 2] = wa.z; Bs[bkk][bcol + 3] = wa.w;
            Bs[bkk][bcol + 4] = wb.x; Bs[bkk][bcol + 5] = wb.y;
            Bs[bkk][bcol + 6] = wb.z; Bs[bkk][bcol + 7] = wb.w;
            __syncthreads();

#pragma unroll
            for (int kk = 0; kk < 16; ++kk) {
                float af[8], bf[8];
                *(float4*)(af)     = *(const float4*)&As[kk][ty * 8];
                *(float4*)(af + 4) = *(const float4*)&As[kk][ty * 8 + 4];
                *(float4*)(bf)     = *(const float4*)&Bs[kk][tx * 8];
                *(float4*)(bf + 4) = *(const float4*)&Bs[kk][tx * 8 + 4];
#pragma unroll
                for (int i = 0; i < 8; ++i)
#pragma unroll
                    for (int j = 0; j < 8; ++j) acc[i][j] += af[i] * bf[j];
            }
        }
    }

    float bv[8];
    *(float4*)(bv)     = *(const float4*)(bias + tx * 8);
    *(float4*)(bv + 4) = *(const float4*)(bias + tx * 8 + 4);
#pragma unroll
    for (int i = 0; i < 8; ++i) {
        int r = row0 + ty * 8 + i;
        if (r < ne) {
            float o[8];
#pragma unroll
            for (int j = 0; j < 8; ++j) o[j] = fmaxf(acc[i][j] + bv[j], 0.0f);
            *(float4*)(g_he + (size_t)r * FH + tx * 8)     = *(float4*)(o);
            *(float4*)(g_he + (size_t)r * FH + tx * 8 + 4) = *(float4*)(o + 4);
        }
    }
}

// ---------------- final score: sigmoid(he . lin2W + b), one warp per edge ----------------
__global__ void score_kernel(const float* __restrict__ lin2W, const float* __restrict__ lin2b,
                             float* __restrict__ out, int ne) {
    int e = (blockIdx.x * blockDim.x + threadIdx.x) >> 5;
    if (e >= ne) return;
    int lane = threadIdx.x & 31;
    float4 v = *(const float4*)(g_he + (size_t)e * FH + lane * 4);
    float4 w = *(const float4*)(lin2W + lane * 4);
    float p = v.x * w.x + v.y * w.y + v.z * w.z + v.w * w.w;
#pragma unroll
    for (int o = 16; o; o >>= 1) p += __shfl_xor_sync(0xffffffffu, p, o);
    if (lane == 0) out[e] = 1.0f / (1.0f + expf(-(p + lin2b[0])));
}

// ---------------- host ----------------
extern "C" void kernel_launch(void* const* d_in, const int* in_sizes, int n_in,
                              void* d_out, int out_size) {
    const float* x    = (const float*)d_in[0];
    const float* Ws1  = (const float*)d_in[1];
    const float* b1   = (const float*)d_in[2];
    const float* Wn1  = (const float*)d_in[3];
    const float* Ws2  = (const float*)d_in[4];
    const float* b2   = (const float*)d_in[5];
    const float* Wn2  = (const float*)d_in[6];
    const float* attW = (const float*)d_in[7];
    const float* attB = (const float*)d_in[8];
    const float* l1W  = (const float*)d_in[9];
    const float* l1b  = (const float*)d_in[10];
    const float* l2W  = (const float*)d_in[11];
    const float* l2b  = (const float*)d_in[12];
    const int* srcs[4] = {(const int*)d_in[13], (const int*)d_in[15],
                          (const int*)d_in[17], (const int*)d_in[19]};
    const int* dsts[4] = {(const int*)d_in[14], (const int*)d_in[16],
                          (const int*)d_in[18], (const int*)d_in[20]};
    const int* ssim = (const int*)d_in[21];
    const int* dsim = (const int*)d_in[22];
    const int  esim = in_sizes[21];

    void *aggP = nullptr, *degP = nullptr, *h1P = nullptr, *hsP = nullptr;
    cudaGetSymbolAddress(&aggP, g_agg);
    cudaGetSymbolAddress(&degP, g_deg);
    cudaGetSymbolAddress(&h1P, g_h1);
    cudaGetSymbolAddress(&hsP, g_hstack);

    const int NB_GEMM = (NN + 127) / 128;

    for (int k = 0; k < 4; ++k) {
        const int ne = in_sizes[13 + 2 * k];
        // degree (same for both layers of this metapath)
        cudaMemsetAsync(degP, 0, NN * sizeof(float));
        deg_kernel<<<(ne + 255) / 256, 256>>>(dsts[k], ne);
        invdeg_kernel<<<(NN + 255) / 256, 256>>>();

        // layer 1
        cudaMemsetAsync(aggP, 0, (size_t)NN * FH * sizeof(float));
        scatter_kernel<<<(ne * 32 + 255) / 256, 256>>>(x, srcs[k], dsts[k], ne);
        sage_gemm_kernel<true><<<NB_GEMM, 256>>>(
            x, Ws1 + (size_t)k * FH * FH, Wn1 + (size_t)k * FH * FH,
            b1 + (size_t)k * FH, (float*)h1P, NN);

        // layer 2
        cudaMemsetAsync(aggP, 0, (size_t)NN * FH * sizeof(float));
        scatter_kernel<<<(ne * 32 + 255) / 256, 256>>>((const float*)h1P, srcs[k], dsts[k], ne);
        sage_gemm_kernel<false><<<NB_GEMM, 256>>>(
            (const float*)h1P, Ws2 + (size_t)k * FH * FH, Wn2 + (size_t)k * FH * FH,
            b2 + (size_t)k * FH, (float*)hsP + (size_t)k * NN * FH, NN);
    }

    attention_kernel<<<(NN * 32 + 255) / 256, 256>>>(attW, attB);
    edge_gemm_kernel<<<(esim + 127) / 128, 256>>>(ssim, dsim, l1W, l1b, esim);
    score_kernel<<<(esim / 8) + 1, 256>>>(l2W, l2b, (float*)d_out, esim);
}

// round 5
// speedup vs baseline: 1.6011x; 1.6011x over previous
#include <cuda_runtime.h>
#include <cuda_bf16.h>
#include <math.h>
#include <stdint.h>

#define NN   50000
#define FH   128

// ===================== scratch (static device globals) =====================
__device__ float         g_agg[(size_t)4 * NN * FH];
__device__ float         g_deg[4 * NN];
__device__ float         g_invdeg[4 * NN];
__device__ float         g_hstack[(size_t)4 * NN * FH];
__device__ __nv_bfloat16 g_xhi[(size_t)NN * FH],       g_xlo[(size_t)NN * FH];
__device__ __nv_bfloat16 g_agghi[(size_t)4 * NN * FH], g_agglo[(size_t)4 * NN * FH];
__device__ __nv_bfloat16 g_h1hi[(size_t)4 * NN * FH],  g_h1lo[(size_t)4 * NN * FH];
__device__ __nv_bfloat16 g_embhi[(size_t)NN * FH],     g_emblo[(size_t)NN * FH];
__device__ __nv_bfloat16 g_whi[18 * 16384], g_wlo[18 * 16384];   // [mat][n][k]

__device__ __forceinline__ void bsplit(float v, __nv_bfloat16& h, __nv_bfloat16& l) {
    h = __float2bfloat16(v);
    l = __float2bfloat16(v - __bfloat162float(h));
}
__device__ __forceinline__ uint32_t pack_bf16(__nv_bfloat16 a, __nv_bfloat16 b) {
    return (uint32_t)__bfloat16_as_ushort(a) | ((uint32_t)__bfloat16_as_ushort(b) << 16);
}
__device__ __forceinline__ void red_add_v4(float* p, float a, float b, float c, float d) {
    asm volatile("red.global.add.v4.f32 [%0], {%1, %2, %3, %4};"
                 :: "l"(p), "f"(a), "f"(b), "f"(c), "f"(d) : "memory");
}
__device__ __forceinline__ uint32_t smem_u32(const void* p) {
    uint32_t a;
    asm("{ .reg .u64 t; cvta.to.shared.u64 t, %1; cvt.u32.u64 %0, t; }" : "=r"(a) : "l"(p));
    return a;
}
__device__ __forceinline__ uint32_t swz(uint32_t off) { return off ^ ((off >> 3) & 0x70); }

__device__ __forceinline__ void ldm_x4(uint32_t addr, uint32_t* r) {
    asm volatile("ldmatrix.sync.aligned.m8n8.x4.shared.b16 {%0,%1,%2,%3}, [%4];"
                 : "=r"(r[0]), "=r"(r[1]), "=r"(r[2]), "=r"(r[3]) : "r"(addr));
}
__device__ __forceinline__ void mma16816(float* c, const uint32_t* a, const uint32_t* b) {
    asm volatile("mma.sync.aligned.m16n8k16.row.col.f32.bf16.bf16.f32 "
        "{%0,%1,%2,%3}, {%4,%5,%6,%7}, {%8,%9}, {%0,%1,%2,%3};"
        : "+f"(c[0]), "+f"(c[1]), "+f"(c[2]), "+f"(c[3])
        : "r"(a[0]), "r"(a[1]), "r"(a[2]), "r"(a[3]), "r"(b[0]), "r"(b[1]));
}

// ===================== small kernels =====================
__global__ void split_weights_kernel(const float* __restrict__ Ws1, const float* __restrict__ Wn1,
                                     const float* __restrict__ Ws2, const float* __restrict__ Wn2,
                                     const float* __restrict__ L1) {
    int g = blockIdx.x * blockDim.x + threadIdx.x;
    if (g >= 18 * 16384) return;
    int m = g >> 14, r = g & 16383, n = r >> 7, k = r & 127;
    const float* s;
    if (m < 4)       s = Ws1 + (size_t)m * 16384;
    else if (m < 8)  s = Wn1 + (size_t)(m - 4) * 16384;
    else if (m < 12) s = Ws2 + (size_t)(m - 8) * 16384;
    else if (m < 16) s = Wn2 + (size_t)(m - 12) * 16384;
    else             s = L1  + (size_t)(m - 16) * 16384;
    float v = s[k * 128 + n];                 // transpose [k][n] -> [n][k]
    __nv_bfloat16 h, l; bsplit(v, h, l);
    g_whi[(size_t)m * 16384 + n * 128 + k] = h;
    g_wlo[(size_t)m * 16384 + n * 128 + k] = l;
}

// split f32 rows -> bf16 hi/lo, optional per-row invdeg scale; grid.y = metapath
__global__ void split_rows_kernel(const float* __restrict__ src, int use_scale,
                                  __nv_bfloat16* __restrict__ hi, __nv_bfloat16* __restrict__ lo) {
    int y = blockIdx.y;
    int i = blockIdx.x * blockDim.x + threadIdx.x;
    if (i >= NN * FH) return;
    size_t o = (size_t)y * NN * FH + i;
    float v = src[o];
    if (use_scale) v *= g_invdeg[y * NN + (i >> 7)];
    __nv_bfloat16 h, l; bsplit(v, h, l);
    hi[o] = h; lo[o] = l;
}

struct EdgeArgs {
    const int* src[4]; const int* dst[4];
    const __nv_bfloat16* rhi[4]; const __nv_bfloat16* rlo[4];
    int ne[4];
};

__global__ void deg_kernel(EdgeArgs a) {
    int y = blockIdx.y;
    int i = blockIdx.x * blockDim.x + threadIdx.x;
    if (i < a.ne[y]) atomicAdd(&g_deg[y * NN + __ldg(a.dst[y] + i)], 1.0f);
}
__global__ void invdeg_kernel() {
    int i = blockIdx.x * blockDim.x + threadIdx.x;
    if (i < 4 * NN) g_invdeg[i] = 1.0f / fmaxf(g_deg[i], 1.0f);
}

// batched scatter: agg[y][dst] += (hi[src]+lo[src]); one warp per edge
__global__ void scatter_kernel(EdgeArgs a) {
    int y = blockIdx.y;
    int w = (blockIdx.x * blockDim.x + threadIdx.x) >> 5;
    if (w >= a.ne[y]) return;
    int lane = threadIdx.x & 31;
    int s = __ldg(a.src[y] + w), d = __ldg(a.dst[y] + w);
    const __nv_bfloat162* ph = (const __nv_bfloat162*)(a.rhi[y] + (size_t)s * FH + lane * 4);
    const __nv_bfloat162* pl = (const __nv_bfloat162*)(a.rlo[y] + (size_t)s * FH + lane * 4);
    float2 h01 = __bfloat1622float2(ph[0]);
    float2 h23 = __bfloat1622float2(ph[1]);
    float2 l01 = __bfloat1622float2(pl[0]);
    float2 l23 = __bfloat1622float2(pl[1]);
    float* p = g_agg + ((size_t)y * NN + d) * FH + lane * 4;
    red_add_v4(p, h01.x + l01.x, h01.y + l01.y, h23.x + l23.x, h23.y + l23.y);
}

// attention softmax over 4 metapaths -> emb bf16 hi/lo; one warp per node
__global__ void attention_kernel(const float* __restrict__ attW, const float* __restrict__ attB) {
    int n = (blockIdx.x * blockDim.x + threadIdx.x) >> 5;
    if (n >= NN) return;
    int lane = threadIdx.x & 31;
    float4 hv[4]; float logit[4];
#pragma unroll
    for (int k = 0; k < 4; ++k) {
        float4 h4 = *(const float4*)(g_hstack + ((size_t)k * NN + n) * FH + lane * 4);
        float4 w4 = *(const float4*)(attW + k * FH + lane * 4);
        hv[k] = h4;
        float p = h4.x * w4.x + h4.y * w4.y + h4.z * w4.z + h4.w * w4.w;
#pragma unroll
        for (int o = 16; o; o >>= 1) p += __shfl_xor_sync(0xffffffffu, p, o);
        logit[k] = p + attB[k];
    }
    float m = fmaxf(fmaxf(logit[0], logit[1]), fmaxf(logit[2], logit[3]));
    float e[4], s = 0.0f;
#pragma unroll
    for (int k = 0; k < 4; ++k) { e[k] = expf(logit[k] - m); s += e[k]; }
    float is = 1.0f / s;
    float4 o = make_float4(0.f, 0.f, 0.f, 0.f);
#pragma unroll
    for (int k = 0; k < 4; ++k) {
        float w = e[k] * is;
        o.x += w * hv[k].x; o.y += w * hv[k].y; o.z += w * hv[k].z; o.w += w * hv[k].w;
    }
    __nv_bfloat16 h0, l0, h1, l1, h2, l2, h3, l3;
    bsplit(o.x, h0, l0); bsplit(o.y, h1, l1); bsplit(o.z, h2, l2); bsplit(o.w, h3, l3);
    *(uint2*)(g_embhi + (size_t)n * FH + lane * 4) = make_uint2(pack_bf16(h0, h1), pack_bf16(h2, h3));
    *(uint2*)(g_emblo + (size_t)n * FH + lane * 4) = make_uint2(pack_bf16(l0, l1), pack_bf16(l2, l3));
}

// ===================== mma.sync GEMM =====================
// D[128 x 128] = sum over 2 halves of bf16-split A_half[rows,128] @ W_half[n=128,k=128]^T
// 3-term split: Ahi*Whi + Ahi*Wlo + Alo*Whi, fp32 accum.
// MODE 0: relu -> bf16 hi/lo.  MODE 1: +bias -> f32.  MODE 2: relu + lin2 dot + sigmoid.
#define SB_BIAS 0
#define SB_L2W  512
#define SB_PART 1024
#define SB_AHI  4096
#define SB_ALO  (4096 + 16384)
#define SB_WHI  (4096 + 2 * 16384)
#define SB_WLO  (4096 + 3 * 16384)
#define SMEM_TOTAL (4096 + 4 * 16384)

// stage a 128x64 bf16 tile (row-major 128B rows) into SW128-swizzled smem; 256 threads
__device__ __forceinline__ void stage_tile(uint32_t stile, const __nv_bfloat16* gbase,
                                           const int* idx, int row0, int nrows, int kofs, int tid) {
#pragma unroll
    for (int i = tid; i < 1024; i += 256) {
        int r = i >> 3, j = i & 7;
        uint4 v = make_uint4(0, 0, 0, 0);
        int grow = row0 + r;
        if (grow < nrows) {
            int row = idx ? __ldg(idx + grow) : grow;
            v = *(const uint4*)(gbase + (size_t)row * FH + kofs + j * 8);
        }
        uint32_t off = (uint32_t)(r * 128 + j * 16);
        asm volatile("st.shared.v4.b32 [%0], {%1,%2,%3,%4};"
                     :: "r"(stile + swz(off)), "r"(v.x), "r"(v.y), "r"(v.z), "r"(v.w));
    }
}

// A fragments: 4 m-frags (64 rows) for one warp; k16 step `ks` within the 64-k tile
__device__ __forceinline__ void load_a(uint32_t tb, int wm, int ks, int lane, uint32_t* ra) {
    int q = lane >> 3, r = lane & 7;
    int rofs = ((q & 1) ? 8 : 0) + r;
    int kl = ks * 16 + ((q & 2) ? 8 : 0);
#pragma unroll
    for (int mf = 0; mf < 4; ++mf) {
        uint32_t off = (uint32_t)((wm * 64 + mf * 16 + rofs) * 128 + kl * 2);
        ldm_x4(tb + swz(off), ra + mf * 4);
    }
}
// W fragments: 4 n-frags (32 cols) for one warp
__device__ __forceinline__ void load_w(uint32_t tb, int wn, int ks, int lane, uint32_t* rw) {
    int q = lane >> 3, r = lane & 7;
    int rofs = ((q & 2) ? 8 : 0) + r;
    int kl = ks * 16 + ((q & 1) ? 8 : 0);
#pragma unroll
    for (int pf = 0; pf < 2; ++pf) {
        uint32_t off = (uint32_t)((wn * 32 + pf * 16 + rofs) * 128 + kl * 2);
        ldm_x4(tb + swz(off), rw + pf * 4);
    }
}

template <int MODE>
__global__ void __launch_bounds__(256) mp_gemm_kernel(
    const __nv_bfloat16* __restrict__ a0hi, const __nv_bfloat16* __restrict__ a0lo,
    const int* __restrict__ idx0, size_t a0stride,
    const __nv_bfloat16* __restrict__ a1hi, const __nv_bfloat16* __restrict__ a1lo,
    const int* __restrict__ idx1, size_t a1stride,
    int w0mat, int w1mat, int wmatstride,
    const float* __restrict__ bias, int bstride,
    const float* __restrict__ l2w, const float* __restrict__ l2b,
    float* __restrict__ outf, size_t outfstride,
    __nv_bfloat16* __restrict__ outhi, __nv_bfloat16* __restrict__ outlo, size_t outbstride,
    int nrows)
{
    extern __shared__ char smem[];
    const uint32_t sb = smem_u32(smem);
    const int tid = threadIdx.x, lane = tid & 31, wid = tid >> 5;
    const int wm = wid & 1, wn = wid >> 1;
    const int y = blockIdx.y;
    const int row0 = blockIdx.x * 128;

    float* sbias = (float*)(smem + SB_BIAS);
    float* sl2w  = (float*)(smem + SB_L2W);
    float* spart = (float*)(smem + SB_PART);   // [128][4]
    if (tid < 128) {
        sbias[tid] = bias[bstride * y + tid];
        if (MODE == 2) sl2w[tid] = l2w[tid];
    }

    const __nv_bfloat16* ahis[2] = { a0hi + (size_t)y * a0stride, a1hi + (size_t)y * a1stride };
    const __nv_bfloat16* alos[2] = { a0lo + (size_t)y * a0stride, a1lo + (size_t)y * a1stride };
    const int* idxs[2] = { idx0, idx1 };
    const int wm0 = w0mat + y * wmatstride, wm1 = w1mat + y * wmatstride;

    float acc[4][4][4];
#pragma unroll
    for (int i = 0; i < 4; ++i)
#pragma unroll
        for (int j = 0; j < 4; ++j)
#pragma unroll
            for (int q = 0; q < 4; ++q) acc[i][j][q] = 0.0f;

#pragma unroll 1
    for (int c = 0; c < 4; ++c) {
        const int half = c >> 1, kc = (c & 1) * 64;
        const __nv_bfloat16* whb = g_whi + (size_t)(half ? wm1 : wm0) * 16384;
        const __nv_bfloat16* wlb = g_wlo + (size_t)(half ? wm1 : wm0) * 16384;
        if (c) __syncthreads();
        stage_tile(sb + SB_AHI, ahis[half], idxs[half], row0, nrows, kc, tid);
        stage_tile(sb + SB_ALO, alos[half], idxs[half], row0, nrows, kc, tid);
        stage_tile(sb + SB_WHI, whb, nullptr, 0, 128, kc, tid);
        stage_tile(sb + SB_WLO, wlb, nullptr, 0, 128, kc, tid);
        __syncthreads();

#pragma unroll
        for (int ks = 0; ks < 4; ++ks) {
            uint32_t ra[16], rwh[8], rwl[8];
            load_a(sb + SB_AHI, wm, ks, lane, ra);
            load_w(sb + SB_WHI, wn, ks, lane, rwh);
#pragma unroll
            for (int mf = 0; mf < 4; ++mf)
#pragma unroll
                for (int nf = 0; nf < 4; ++nf)
                    mma16816(acc[mf][nf], ra + mf * 4, rwh + nf * 2);
            load_w(sb + SB_WLO, wn, ks, lane, rwl);
#pragma unroll
            for (int mf = 0; mf < 4; ++mf)
#pragma unroll
                for (int nf = 0; nf < 4; ++nf)
                    mma16816(acc[mf][nf], ra + mf * 4, rwl + nf * 2);
            load_a(sb + SB_ALO, wm, ks, lane, ra);
#pragma unroll
            for (int mf = 0; mf < 4; ++mf)
#pragma unroll
                for (int nf = 0; nf < 4; ++nf)
                    mma16816(acc[mf][nf], ra + mf * 4, rwh + nf * 2);
        }
    }

    // ---------------- epilogue ----------------
    // fragment mapping: rows = row0 + wm*64 + mf*16 + (lane>>2) [+8]; cols = wn*32 + nf*8 + 2*(lane&3) [+1]
    const int rbase = row0 + wm * 64 + (lane >> 2);
    const int cbase = wn * 32 + 2 * (lane & 3);

    if (MODE == 2) {
        float pr[4][2];
#pragma unroll
        for (int mf = 0; mf < 4; ++mf) { pr[mf][0] = 0.f; pr[mf][1] = 0.f; }
#pragma unroll
        for (int mf = 0; mf < 4; ++mf)
#pragma unroll
            for (int nf = 0; nf < 4; ++nf) {
                int gc = cbase + nf * 8;
                float w0 = sl2w[gc], w1 = sl2w[gc + 1];
                float b0v = sbias[gc], b1v = sbias[gc + 1];
                pr[mf][0] += fmaxf(acc[mf][nf][0] + b0v, 0.f) * w0
                           + fmaxf(acc[mf][nf][1] + b1v, 0.f) * w1;
                pr[mf][1] += fmaxf(acc[mf][nf][2] + b0v, 0.f) * w0
                           + fmaxf(acc[mf][nf][3] + b1v, 0.f) * w1;
            }
#pragma unroll
        for (int mf = 0; mf < 4; ++mf)
#pragma unroll
            for (int hh = 0; hh < 2; ++hh) {
                float p = pr[mf][hh];
                p += __shfl_xor_sync(0xffffffffu, p, 1);
                p += __shfl_xor_sync(0xffffffffu, p, 2);
                if ((lane & 3) == 0)
                    spart[(wm * 64 + mf * 16 + (lane >> 2) + hh * 8) * 4 + wn] = p;
            }
        __syncthreads();
        if (tid < 128) {
            int r = row0 + tid;
            if (r < nrows) {
                float s = spart[tid * 4] + spart[tid * 4 + 1] + spart[tid * 4 + 2] + spart[tid * 4 + 3];
                outf[r] = 1.0f / (1.0f + expf(-(s + l2b[0])));
            }
        }
        return;
    }

#pragma unroll
    for (int mf = 0; mf < 4; ++mf) {
        int r0 = rbase + mf * 16, r1 = r0 + 8;
        bool v0 = r0 < nrows, v1 = r1 < nrows;
#pragma unroll
        for (int nf = 0; nf < 4; ++nf) {
            int gc = cbase + nf * 8;
            float b0v = sbias[gc], b1v = sbias[gc + 1];
            if (MODE == 1) {
                if (v0) *(float2*)(outf + (size_t)y * outfstride + (size_t)r0 * FH + gc)
                        = make_float2(acc[mf][nf][0] + b0v, acc[mf][nf][1] + b1v);
                if (v1) *(float2*)(outf + (size_t)y * outfstride + (size_t)r1 * FH + gc)
                        = make_float2(acc[mf][nf][2] + b0v, acc[mf][nf][3] + b1v);
            } else {
                float e0 = fmaxf(acc[mf][nf][0] + b0v, 0.f), e1 = fmaxf(acc[mf][nf][1] + b1v, 0.f);
                float e2 = fmaxf(acc[mf][nf][2] + b0v, 0.f), e3 = fmaxf(acc[mf][nf][3] + b1v, 0.f);
                __nv_bfloat16 h0, l0, h1, l1, h2, l2, h3, l3;
                bsplit(e0, h0, l0); bsplit(e1, h1, l1); bsplit(e2, h2, l2); bsplit(e3, h3, l3);
                if (v0) {
                    *(uint32_t*)(outhi + (size_t)y * outbstride + (size_t)r0 * FH + gc) = pack_bf16(h0, h1);
                    *(uint32_t*)(outlo + (size_t)y * outbstride + (size_t)r0 * FH + gc) = pack_bf16(l0, l1);
                }
                if (v1) {
                    *(uint32_t*)(outhi + (size_t)y * outbstride + (size_t)r1 * FH + gc) = pack_bf16(h2, h3);
                    *(uint32_t*)(outlo + (size_t)y * outbstride + (size_t)r1 * FH + gc) = pack_bf16(l2, l3);
                }
            }
        }
    }
}

// ===================== host =====================
extern "C" void kernel_launch(void* const* d_in, const int* in_sizes, int n_in,
                              void* d_out, int out_size) {
    const float* x    = (const float*)d_in[0];
    const float* Ws1  = (const float*)d_in[1];
    const float* b1   = (const float*)d_in[2];
    const float* Wn1  = (const float*)d_in[3];
    const float* Ws2  = (const float*)d_in[4];
    const float* b2   = (const float*)d_in[5];
    const float* Wn2  = (const float*)d_in[6];
    const float* attW = (const float*)d_in[7];
    const float* attB = (const float*)d_in[8];
    const float* l1W  = (const float*)d_in[9];
    const float* l1b  = (const float*)d_in[10];
    const float* l2W  = (const float*)d_in[11];
    const float* l2b  = (const float*)d_in[12];
    const int* srcs[4] = {(const int*)d_in[13], (const int*)d_in[15],
                          (const int*)d_in[17], (const int*)d_in[19]};
    const int* dsts[4] = {(const int*)d_in[14], (const int*)d_in[16],
                          (const int*)d_in[18], (const int*)d_in[20]};
    const int* ssim = (const int*)d_in[21];
    const int* dsim = (const int*)d_in[22];
    const int  esim = in_sizes[21];

    void *aggP, *degP, *hsP, *xhiP, *xloP, *agghiP, *aggloP, *h1hiP, *h1loP, *embhiP, *embloP;
    cudaGetSymbolAddress(&aggP, g_agg);
    cudaGetSymbolAddress(&degP, g_deg);
    cudaGetSymbolAddress(&hsP, g_hstack);
    cudaGetSymbolAddress(&xhiP, g_xhi);     cudaGetSymbolAddress(&xloP, g_xlo);
    cudaGetSymbolAddress(&agghiP, g_agghi); cudaGetSymbolAddress(&aggloP, g_agglo);
    cudaGetSymbolAddress(&h1hiP, g_h1hi);   cudaGetSymbolAddress(&h1loP, g_h1lo);
    cudaGetSymbolAddress(&embhiP, g_embhi); cudaGetSymbolAddress(&embloP, g_emblo);

    cudaFuncSetAttribute(mp_gemm_kernel<0>, cudaFuncAttributeMaxDynamicSharedMemorySize, SMEM_TOTAL);
    cudaFuncSetAttribute(mp_gemm_kernel<1>, cudaFuncAttributeMaxDynamicSharedMemorySize, SMEM_TOTAL);
    cudaFuncSetAttribute(mp_gemm_kernel<2>, cudaFuncAttributeMaxDynamicSharedMemorySize, SMEM_TOTAL);

    EdgeArgs ea;
    int max_ne = 0;
    for (int k = 0; k < 4; ++k) {
        ea.src[k] = srcs[k]; ea.dst[k] = dsts[k];
        ea.ne[k] = in_sizes[13 + 2 * k];
        if (ea.ne[k] > max_ne) max_ne = ea.ne[k];
    }

    const int NB = (NN + 127) / 128;
    const size_t NF = (size_t)NN * FH;

    // 0. weight + x splits
    split_weights_kernel<<<(18 * 16384 + 255) / 256, 256>>>(Ws1, Wn1, Ws2, Wn2, l1W);
    split_rows_kernel<<<dim3((NN * FH + 255) / 256, 1), 256>>>(x, 0,
        (__nv_bfloat16*)xhiP, (__nv_bfloat16*)xloP);

    // 1. degrees
    cudaMemsetAsync(degP, 0, 4 * NN * sizeof(float));
    deg_kernel<<<dim3((max_ne + 255) / 256, 4), 256>>>(ea);
    invdeg_kernel<<<(4 * NN + 255) / 256, 256>>>();

    // 2. layer-1 aggregation
    cudaMemsetAsync(aggP, 0, 4 * NF * sizeof(float));
    for (int k = 0; k < 4; ++k) { ea.rhi[k] = (const __nv_bfloat16*)xhiP; ea.rlo[k] = (const __nv_bfloat16*)xloP; }
    scatter_kernel<<<dim3((max_ne + 7) / 8, 4), 256>>>(ea);
    split_rows_kernel<<<dim3((NN * FH + 255) / 256, 4), 256>>>((const float*)aggP, 1,
        (__nv_bfloat16*)agghiP, (__nv_bfloat16*)aggloP);

    // 3. layer-1 GEMM: h1 = relu(x@Ws1 + aggn@Wn1 + b1) -> bf16 hi/lo
    mp_gemm_kernel<0><<<dim3(NB, 4), 256, SMEM_TOTAL>>>(
        (const __nv_bfloat16*)xhiP, (const __nv_bfloat16*)xloP, nullptr, 0,
        (const __nv_bfloat16*)agghiP, (const __nv_bfloat16*)aggloP, nullptr, NF,
        0, 4, 1, b1, FH, nullptr, nullptr,
        nullptr, 0, (__nv_bfloat16*)h1hiP, (__nv_bfloat16*)h1loP, NF, NN);

    // 4. layer-2 aggregation
    cudaMemsetAsync(aggP, 0, 4 * NF * sizeof(float));
    for (int k = 0; k < 4; ++k) {
        ea.rhi[k] = (const __nv_bfloat16*)h1hiP + (size_t)k * NF;
        ea.rlo[k] = (const __nv_bfloat16*)h1loP + (size_t)k * NF;
    }
    scatter_kernel<<<dim3((max_ne + 7) / 8, 4), 256>>>(ea);
    split_rows_kernel<<<dim3((NN * FH + 255) / 256, 4), 256>>>((const float*)aggP, 1,
        (__nv_bfloat16*)agghiP, (__nv_bfloat16*)aggloP);

    // 5. layer-2 GEMM -> f32 hstack
    mp_gemm_kernel<1><<<dim3(NB, 4), 256, SMEM_TOTAL>>>(
        (const __nv_bfloat16*)h1hiP, (const __nv_bfloat16*)h1loP, nullptr, NF,
        (const __nv_bfloat16*)agghiP, (const __nv_bfloat16*)aggloP, nullptr, NF,
        8, 12, 1, b2, FH, nullptr, nullptr,
        (float*)hsP, NF, nullptr, nullptr, 0, NN);

    // 6. attention -> emb bf16 hi/lo
    attention_kernel<<<(NN * 32 + 255) / 256, 256>>>(attW, attB);

    // 7. fused edge scorer: gather-GEMM + relu + lin2 dot + sigmoid
    mp_gemm_kernel<2><<<dim3((esim + 127) / 128, 1), 256, SMEM_TOTAL>>>(
        (const __nv_bfloat16*)embhiP, (const __nv_bfloat16*)embloP, ssim, 0,
        (const __nv_bfloat16*)embhiP, (const __nv_bfloat16*)embloP, dsim, 0,
        16, 17, 0, l1b, 0, l2W, l2b,
        (float*)d_out, 0, nullptr, nullptr, 0, esim);
}